// round 13
// baseline (speedup 1.0000x reference)
#include <cuda_runtime.h>
#include <cuda_bf16.h>
#include <math.h>

#define HW 200704
#define CC 192
#define NHEAD 6

// ---------------- scratch ----------------
__device__ float g_mu[HW];
__device__ float g_rstd[HW];
__device__ float g_Wf[576 * CC];
__device__ float g_bias[576];
__device__ float g_G[CC * CC];
__device__ float g_s[CC];
__device__ float g_T[384 * CC];
__device__ float g_u[384];
__device__ __align__(16) __nv_bfloat16 g_Wvf[CC * CC];   // v weight, mma-fragment order
__device__ __align__(16) __nv_bfloat16 g_Wpf[CC * CC];   // proj weight, mma-fragment order
__device__ __align__(16) __nv_bfloat16 g_gmf[CC * 32];   // gm blocks, fragment order [h][ks*2+mt][lane][4x2]

// fragment scatter index: A m16n8k16 row-major bf16 fragment layout
__device__ __forceinline__ int frag_idx(int o, int j) {
    int mt = o >> 4, kt = j >> 4;
    int om = o & 15, jm = j & 15;
    int gid = om & 7, hi_m = om >> 3;
    int tig = (jm & 7) >> 1, hi_k = jm >> 3, par = jm & 1;
    int lane = gid * 4 + tig;
    return (((kt * 12 + mt) * 32 + lane) << 3) + ((hi_m + 2 * hi_k) << 1) + par;
}

// ---------------- mma / ldmatrix helpers ----------------
__device__ __forceinline__ void mma16816(float* c, const unsigned* a, const unsigned* b) {
    asm volatile(
        "mma.sync.aligned.m16n8k16.row.col.f32.bf16.bf16.f32 "
        "{%0,%1,%2,%3},{%4,%5,%6,%7},{%8,%9},{%0,%1,%2,%3};\n"
        : "+f"(c[0]), "+f"(c[1]), "+f"(c[2]), "+f"(c[3])
        : "r"(a[0]), "r"(a[1]), "r"(a[2]), "r"(a[3]), "r"(b[0]), "r"(b[1]));
}

__device__ __forceinline__ void ldsm4(unsigned* r, unsigned a) {
    asm volatile("ldmatrix.sync.aligned.m8n8.x4.shared.b16 {%0,%1,%2,%3}, [%4];"
                 : "=r"(r[0]), "=r"(r[1]), "=r"(r[2]), "=r"(r[3]) : "r"(a));
}

// ---------------- LN stats + zero accumulators + proj_w fragment convert ---------
__global__ void k_stats(const float* __restrict__ x, const float* __restrict__ proj_w) {
    int i = blockIdx.x * 256 + threadIdx.x;
    if (i < CC * CC) {
        g_G[i] = 0.f;
        int o = i / CC, j = i - o * CC;
        g_Wpf[frag_idx(o, j)] = __float2bfloat16(proj_w[i]);
    }
    if (i < CC) g_s[i] = 0.f;
    int p = i;
    float s = 0.f, ss = 0.f;
#pragma unroll 8
    for (int c = 0; c < CC; c++) {
        float v = x[c * HW + p];
        s += v; ss += v * v;
    }
    float mu  = s * (1.f / CC);
    float var = ss * (1.f / CC) - mu * mu;
    g_mu[p]   = mu;
    g_rstd[p] = rsqrtf(var + 1e-5f);
}

// ---------------- fold weights ----------------
__global__ void k_fold(const float* __restrict__ qkv_w, const float* __restrict__ pre_w,
                       const float* __restrict__ ln_g, const float* __restrict__ ln_b,
                       const float* __restrict__ pre_b) {
    int o = blockIdx.x, j = threadIdx.x;
    float w2 = 0.f;
#pragma unroll 4
    for (int c = 0; c < CC; c++) w2 += qkv_w[o * CC + c] * pre_w[c * CC + j];
    float wf = w2 * ln_g[j];
    g_Wf[o * CC + j] = wf;
    if (o >= 384) g_Wvf[frag_idx(o - 384, j)] = __float2bfloat16(wf);
    __shared__ float s2[CC];
    s2[j] = w2 * ln_b[j] + qkv_w[o * CC + j] * pre_b[j];
    __syncthreads();
    if (j < 64) s2[j] += s2[j + 64] + s2[j + 128];
    __syncthreads();
    if (j < 32) {
        float b = s2[j] + s2[j + 32];
#pragma unroll
        for (int off = 16; off > 0; off >>= 1) b += __shfl_down_sync(0xffffffffu, b, off);
        if (j == 0) g_bias[o] = b;
    }
}

// ---------------- Gram of xhat: persistent, 64-pixel tiles, 384 threads ----------
#define NT64 (HW / 64)
__global__ __launch_bounds__(384) void k_gram(const float* __restrict__ x) {
    extern __shared__ __align__(16) unsigned short xs[];   // [2][CC][72]
    int tid = threadIdx.x;
    int warp = tid >> 5, lane = tid & 31, gid = lane >> 2, tig = lane & 3;
    int m0 = (warp & 3) * 48;
    int n0 = (warp >> 2) * 64;
    float acc[3][8][4];
#pragma unroll
    for (int f = 0; f < 3; f++)
#pragma unroll
        for (int g = 0; g < 8; g++)
#pragma unroll
            for (int r = 0; r < 4; r++) acc[f][g][r] = 0.f;
    float srow[8];
#pragma unroll
    for (int i = 0; i < 8; i++) srow[i] = 0.f;

    auto load_half = [&](int t, int b, int h) {
        int p0 = t * 64;
#pragma unroll
        for (int i = 0; i < 4; i++) {
            int q = tid + 384 * (h * 4 + i);
            int c = q >> 4, seg = q & 15;
            int p = p0 + seg * 4;
            float4 xv = *(const float4*)(x + c * HW + p);
            float4 m4 = *(const float4*)(g_mu + p);
            float4 r4 = *(const float4*)(g_rstd + p);
            float h0 = (xv.x - m4.x) * r4.x;
            float h1 = (xv.y - m4.y) * r4.y;
            float h2 = (xv.z - m4.z) * r4.z;
            float h3 = (xv.w - m4.w) * r4.w;
            __nv_bfloat162 lo = __floats2bfloat162_rn(h0, h1);
            __nv_bfloat162 hi = __floats2bfloat162_rn(h2, h3);
            uint2 u;
            u.x = *(unsigned*)&lo;
            u.y = *(unsigned*)&hi;
            *(uint2*)(xs + (b * CC + c) * 72 + seg * 4) = u;
            srow[h * 4 + i] += h0 + h1 + h2 + h3;
        }
    };

    int t = blockIdx.x;
    int iter = 0;
    load_half(t, 0, 0);
    load_half(t, 0, 1);
    __syncthreads();
    while (t < NT64) {
        int b = iter & 1;
        int tn = t + gridDim.x;
        if (tn < NT64) { load_half(tn, b ^ 1, 0); load_half(tn, b ^ 1, 1); }
#pragma unroll
        for (int ks = 0; ks < 4; ks++) {
            int kl = ks * 16 + 2 * tig;
            unsigned a[3][4];
#pragma unroll
            for (int f = 0; f < 3; f++) {
                int r = m0 + f * 16 + gid;
                a[f][0] = *(const unsigned*)&xs[(b * CC + r) * 72 + kl];
                a[f][1] = *(const unsigned*)&xs[(b * CC + r + 8) * 72 + kl];
                a[f][2] = *(const unsigned*)&xs[(b * CC + r) * 72 + kl + 8];
                a[f][3] = *(const unsigned*)&xs[(b * CC + r + 8) * 72 + kl + 8];
            }
#pragma unroll
            for (int g = 0; g < 8; g++) {
                int n = n0 + g * 8 + gid;
                unsigned bb[2];
                bb[0] = *(const unsigned*)&xs[(b * CC + n) * 72 + kl];
                bb[1] = *(const unsigned*)&xs[(b * CC + n) * 72 + kl + 8];
#pragma unroll
                for (int f = 0; f < 3; f++) mma16816(acc[f][g], a[f], bb);
            }
        }
        __syncthreads();
        t = tn; iter++;
    }
#pragma unroll
    for (int f = 0; f < 3; f++) {
        int m = m0 + f * 16 + gid;
#pragma unroll
        for (int g = 0; g < 8; g++) {
            int n = n0 + g * 8 + 2 * tig;
            atomicAdd(&g_G[m * CC + n],           acc[f][g][0]);
            atomicAdd(&g_G[m * CC + n + 1],       acc[f][g][1]);
            atomicAdd(&g_G[(m + 8) * CC + n],     acc[f][g][2]);
            atomicAdd(&g_G[(m + 8) * CC + n + 1], acc[f][g][3]);
        }
    }
#pragma unroll
    for (int i = 0; i < 8; i++) atomicAdd(&g_s[(tid + 384 * i) >> 4], srow[i]);
}

// ---------------- T = W_{q,k} @ G ; u = W_{q,k} @ s (parallel, 384 blocks) -------
__global__ void k_T() {
    int o = blockIdx.x, j = threadIdx.x;
    float acc = 0.f;
#pragma unroll 4
    for (int c = 0; c < CC; c++) acc += g_Wf[o * CC + c] * g_G[c * CC + j];
    g_T[o * CC + j] = acc;
    __shared__ float sh[CC];
    sh[j] = g_Wf[o * CC + j] * g_s[j];
    __syncthreads();
    if (j < 64) sh[j] += sh[j + 64] + sh[j + 128];
    __syncthreads();
    if (j < 32) {
        float a = sh[j] + sh[j + 32];
#pragma unroll
        for (int off = 16; off > 0; off >>= 1) a += __shfl_down_sync(0xffffffffu, a, off);
        if (j == 0) g_u[o] = a;
    }
}

// ---------------- attn -> mn -> gating -> gm (fragment-order bf16) ---------------
__global__ __launch_bounds__(1024) void k_gm(const float* __restrict__ mn_w,
                                             const float* __restrict__ gating) {
    int h = blockIdx.x, tid = threadIdx.x;
    int d = tid >> 5, e = tid & 31;
    __shared__ float attn[32][33];
    __shared__ float nq[32], nk[32];
    if (tid < 64) {
        int o = (tid < 32) ? (h * 32 + tid) : (CC + h * 32 + (tid - 32));
        float acc = 0.f;
        for (int c2 = 0; c2 < CC; c2++) acc += g_T[o * CC + c2] * g_Wf[o * CC + c2];
        float b = g_bias[o];
        acc += 2.f * b * g_u[o] + (float)HW * b * b;
        float nval = fmaxf(sqrtf(fmaxf(acc, 0.f)), 1e-12f);
        if (tid < 32) nq[tid] = nval; else nk[tid - 32] = nval;
    }
    __syncthreads();
    int oq = h * 32 + d, ok = CC + h * 32 + e;
    float acc = 0.f;
    for (int c2 = 0; c2 < CC; c2++) acc += g_T[oq * CC + c2] * g_Wf[ok * CC + c2];
    acc += g_bias[ok] * g_u[oq] + g_bias[oq] * g_u[ok] + (float)HW * g_bias[oq] * g_bias[ok];
    attn[d][e] = acc / (nq[d] * nk[e]);
    __syncthreads();
    float g1 = gating[h], g2 = gating[NHEAD + h];
    float acc2 = 0.f;
#pragma unroll
    for (int e2 = 0; e2 < 32; e2++)
        acc2 += attn[d][e2] * (g1 * mn_w[e * 32 + e2] + g2 * mn_w[(32 + e) * 32 + e2]);
    // scatter into fragment order: [h][ks*2+mt][lane][(hi_m+2*hi_k)*2+par]
    {
        int mt = d >> 4, ks = e >> 4;
        int om = d & 15, jm = e & 15;
        int gid2 = om & 7, hi_m = om >> 3;
        int tig2 = (jm & 7) >> 1, hi_k = jm >> 3, par = jm & 1;
        int lane2 = gid2 * 4 + tig2;
        g_gmf[h * 1024 + ((ks * 2 + mt) * 32 + lane2) * 8 + (hi_m + 2 * hi_k) * 2 + par] =
            __float2bfloat16(acc2);
    }
}

// ---------------- fused kernel: LDG.128 weights + ldmatrix B-fragments -----------
// smem: XH[64][200]bf16 @0, CD[64][200]bf16 @25600, TS[64][196]f32 @51200 = 101376 B
__global__ __launch_bounds__(256, 2) void k_fused(const float* __restrict__ x,
                                                  const float* __restrict__ cond,
                                                  float* __restrict__ out) {
    extern __shared__ __align__(16) char smr[];
    unsigned short* XH = (unsigned short*)(smr);
    unsigned short* CD = (unsigned short*)(smr + 25600);
    float* TS = (float*)(smr + 51200);
    int tid = threadIdx.x;
    int p0 = blockIdx.x * 64;
    int warp = tid >> 5, lane = tid & 31, gid = lane >> 2, tig = lane & 3;
    int m0 = (warp >> 1) * 48, n0 = (warp & 1) * 32;
    int mt0 = (warp >> 1) * 3;
    // ldmatrix per-lane row addresses: matrix msel = lane>>3 -> (g = msel>>1, khalf = msel&1)
    unsigned su = (unsigned)__cvta_generic_to_shared(smr);
    int mrow = lane & 7, msel = lane >> 3;
    unsigned bA  = su + (unsigned)((n0 + ((msel >> 1) << 3) + mrow) * 400 + (msel & 1) * 16);
    unsigned bA2 = bA + 6400;          // g += 2  (16 rows * 400B)
    unsigned bC  = bA + 25600;
    unsigned bC2 = bA2 + 25600;

    // ---- stage xhat (bf16) and cond (bf16), pixel-major [n][c] ----
#pragma unroll
    for (int q = tid; q < 1536; q += 256) {
        int c  = (q >> 4) * 2;
        int n4 = (q & 15) * 4;
        float4 mu4 = *(const float4*)(g_mu + p0 + n4);
        float4 rs4 = *(const float4*)(g_rstd + p0 + n4);
        float4 xa = *(const float4*)(x + c * HW + p0 + n4);
        float4 xb = *(const float4*)(x + (c + 1) * HW + p0 + n4);
        float4 ca = *(const float4*)(cond + c * HW + p0 + n4);
        float4 cb = *(const float4*)(cond + (c + 1) * HW + p0 + n4);
        float mus[4] = {mu4.x, mu4.y, mu4.z, mu4.w};
        float rss[4] = {rs4.x, rs4.y, rs4.z, rs4.w};
        float xas[4] = {xa.x, xa.y, xa.z, xa.w};
        float xbs[4] = {xb.x, xb.y, xb.z, xb.w};
        float cas[4] = {ca.x, ca.y, ca.z, ca.w};
        float cbs[4] = {cb.x, cb.y, cb.z, cb.w};
#pragma unroll
        for (int j = 0; j < 4; j++) {
            __nv_bfloat162 hx = __floats2bfloat162_rn((xas[j] - mus[j]) * rss[j],
                                                      (xbs[j] - mus[j]) * rss[j]);
            *(unsigned*)&XH[(n4 + j) * 200 + c] = *(unsigned*)&hx;
            __nv_bfloat162 hc = __floats2bfloat162_rn(cas[j], cbs[j]);
            *(unsigned*)&CD[(n4 + j) * 200 + c] = *(unsigned*)&hc;
        }
    }
    __syncthreads();

    // ---- GEMM1: v = Wv @ xhat (LDG.128 A, ldmatrix B) ----
    float accv[3][4][4];
#pragma unroll
    for (int f = 0; f < 3; f++)
#pragma unroll
        for (int g = 0; g < 4; g++)
#pragma unroll
            for (int r = 0; r < 4; r++) accv[f][g][r] = 0.f;
#pragma unroll
    for (int kt = 0; kt < 12; kt++) {
        uint4 a[3];
#pragma unroll
        for (int f = 0; f < 3; f++)
            a[f] = *(const uint4*)&g_Wvf[(((kt * 12) + (mt0 + f)) * 32 + lane) * 8];
        unsigned rB[8];
        ldsm4(rB, bA + kt * 32);
        ldsm4(rB + 4, bA2 + kt * 32);
#pragma unroll
        for (int g = 0; g < 4; g++)
#pragma unroll
            for (int f = 0; f < 3; f++)
                mma16816(accv[f][g], (const unsigned*)&a[f], rB + g * 2);
    }

    // ---- GEMM2 (f-wise, block-diag gm, fragment-order A, ldmatrix B) ----
#pragma unroll
    for (int f = 0; f < 3; f++) {
        float accm[4][4];
#pragma unroll
        for (int g = 0; g < 4; g++)
#pragma unroll
            for (int r = 0; r < 4; r++) accm[g][r] = 0.f;
        int row16 = m0 + f * 16;
        int h = row16 >> 5;
        int mt = (row16 >> 4) & 1;
        unsigned kbyte = (unsigned)(((row16 >> 5) << 5) * 2);   // head-aligned k base, bytes
        const __nv_bfloat16* gbase = g_gmf + h * 1024;
#pragma unroll
        for (int ks = 0; ks < 2; ks++) {
            uint4 av = *(const uint4*)&gbase[((ks * 2 + mt) * 32 + lane) * 8];
            unsigned rB[8];
            ldsm4(rB, bC + kbyte + ks * 32);
            ldsm4(rB + 4, bC2 + kbyte + ks * 32);
#pragma unroll
            for (int g = 0; g < 4; g++)
                mma16816(accm[g], (const unsigned*)&av, rB + g * 2);
        }
        float bv0 = g_bias[384 + row16 + gid];
        float bv1 = g_bias[384 + row16 + gid + 8];
#pragma unroll
        for (int g = 0; g < 4; g++) {
            accv[f][g][0] = accm[g][0] * (accv[f][g][0] + bv0);
            accv[f][g][1] = accm[g][1] * (accv[f][g][1] + bv0);
            accv[f][g][2] = accm[g][2] * (accv[f][g][2] + bv1);
            accv[f][g][3] = accm[g][3] * (accv[f][g][3] + bv1);
        }
    }

    // ---- t -> TS ----
#pragma unroll
    for (int f = 0; f < 3; f++) {
        int m = m0 + f * 16 + gid;
#pragma unroll
        for (int g = 0; g < 4; g++) {
            int n = n0 + g * 8 + 2 * tig;
            TS[n * 196 + m]           = accv[f][g][0];
            TS[(n + 1) * 196 + m]     = accv[f][g][1];
            TS[n * 196 + m + 8]       = accv[f][g][2];
            TS[(n + 1) * 196 + m + 8] = accv[f][g][3];
        }
    }
    __syncthreads();

    // ---- softmax over head-dim per pixel (vectorized LDS.128/STS.128) ----
    for (int task = tid; task < 384; task += 256) {
        int h = task >> 6, n = task & 63;
        const float* tb = TS + n * 196 + h * 32;
        float4 t4[8];
#pragma unroll
        for (int k = 0; k < 8; k++) t4[k] = *(const float4*)(tb + 4 * k);
        float mx = -1e30f;
#pragma unroll
        for (int k = 0; k < 8; k++)
            mx = fmaxf(mx, fmaxf(fmaxf(t4[k].x, t4[k].y), fmaxf(t4[k].z, t4[k].w)));
        float s = 0.f;
#pragma unroll
        for (int k = 0; k < 8; k++) {
            t4[k].x = __expf(t4[k].x - mx); t4[k].y = __expf(t4[k].y - mx);
            t4[k].z = __expf(t4[k].z - mx); t4[k].w = __expf(t4[k].w - mx);
            s += t4[k].x + t4[k].y + t4[k].z + t4[k].w;
        }
        float inv = 1.f / s;
        unsigned short* xb = XH + n * 200 + h * 32;
#pragma unroll
        for (int j = 0; j < 4; j++) {
            __nv_bfloat162 q0 = __floats2bfloat162_rn(t4[2 * j].x * inv, t4[2 * j].y * inv);
            __nv_bfloat162 q1 = __floats2bfloat162_rn(t4[2 * j].z * inv, t4[2 * j].w * inv);
            __nv_bfloat162 q2 = __floats2bfloat162_rn(t4[2 * j + 1].x * inv, t4[2 * j + 1].y * inv);
            __nv_bfloat162 q3 = __floats2bfloat162_rn(t4[2 * j + 1].z * inv, t4[2 * j + 1].w * inv);
            uint4 u;
            u.x = *(unsigned*)&q0; u.y = *(unsigned*)&q1;
            u.z = *(unsigned*)&q2; u.w = *(unsigned*)&q3;
            *(uint4*)(xb + j * 8) = u;
        }
    }
    __syncthreads();

    // ---- GEMM3: out = proj @ probs + x (LDG.128 A, ldmatrix B) ----
    float acc[3][4][4];
#pragma unroll
    for (int f = 0; f < 3; f++)
#pragma unroll
        for (int g = 0; g < 4; g++)
#pragma unroll
            for (int r = 0; r < 4; r++) acc[f][g][r] = 0.f;
#pragma unroll
    for (int kt = 0; kt < 12; kt++) {
        uint4 a[3];
#pragma unroll
        for (int f = 0; f < 3; f++)
            a[f] = *(const uint4*)&g_Wpf[(((kt * 12) + (mt0 + f)) * 32 + lane) * 8];
        unsigned rB[8];
        ldsm4(rB, bA + kt * 32);
        ldsm4(rB + 4, bA2 + kt * 32);
#pragma unroll
        for (int g = 0; g < 4; g++)
#pragma unroll
            for (int f = 0; f < 3; f++)
                mma16816(acc[f][g], (const unsigned*)&a[f], rB + g * 2);
    }
#pragma unroll
    for (int f = 0; f < 3; f++) {
        int m = m0 + f * 16 + gid;
#pragma unroll
        for (int g = 0; g < 4; g++) {
            int n = n0 + g * 8 + 2 * tig;
            float2 r0 = *(const float2*)(x + m * HW + p0 + n);
            float2 r1 = *(const float2*)(x + (m + 8) * HW + p0 + n);
            float2 o0 = make_float2(acc[f][g][0] + r0.x, acc[f][g][1] + r0.y);
            float2 o1 = make_float2(acc[f][g][2] + r1.x, acc[f][g][3] + r1.y);
            *(float2*)(out + m * HW + p0 + n) = o0;
            *(float2*)(out + (m + 8) * HW + p0 + n) = o1;
        }
    }
}

// ---------------- launch ----------------
extern "C" void kernel_launch(void* const* d_in, const int* in_sizes, int n_in,
                              void* d_out, int out_size) {
    const float* x      = (const float*)d_in[0];
    const float* cond   = (const float*)d_in[1];
    const float* ln_g   = (const float*)d_in[2];
    const float* ln_b   = (const float*)d_in[3];
    const float* pre_w  = (const float*)d_in[4];
    const float* pre_b  = (const float*)d_in[5];
    const float* qkv_w  = (const float*)d_in[6];
    const float* mn_w   = (const float*)d_in[7];
    const float* gating = (const float*)d_in[8];
    const float* proj_w = (const float*)d_in[9];
    float* out = (float*)d_out;

    cudaFuncSetAttribute(k_fused, cudaFuncAttributeMaxDynamicSharedMemorySize, 101376);
    cudaFuncSetAttribute(k_gram, cudaFuncAttributeMaxDynamicSharedMemorySize, 55296);

    k_stats<<<HW / 256, 256>>>(x, proj_w);                  // 1 (+zero +cvt)
    k_fold<<<576, CC>>>(qkv_w, pre_w, ln_g, ln_b, pre_b);   // 2
    k_gram<<<148, 384, 55296>>>(x);                         // 3
    k_T<<<384, CC>>>();                                     // 4
    k_gm<<<NHEAD, 1024>>>(mn_w, gating);                    // 5
    k_fused<<<HW / 64, 256, 101376>>>(x, cond, out);        // 6
}

// round 16
// speedup vs baseline: 1.3931x; 1.3931x over previous
#include <cuda_runtime.h>
#include <cuda_bf16.h>
#include <math.h>

#define HW 200704
#define CC 192
#define NHEAD 6

// ---------------- scratch ----------------
__device__ float g_mu[HW];
__device__ float g_rstd[HW];
__device__ float g_Wf[576 * CC];
__device__ float g_bias[576];
__device__ float g_G[CC * CC];
__device__ float g_s[CC];
__device__ float g_T[384 * CC];
__device__ float g_u[384];
__device__ __align__(16) __nv_bfloat16 g_Wvf[CC * CC];   // v weight, mma-fragment order
__device__ __align__(16) __nv_bfloat16 g_Wpf[CC * CC];   // proj weight, mma-fragment order
__device__ __align__(16) __nv_bfloat16 g_gmf[CC * 32];   // gm blocks, fragment order [h][ks*2+mt][lane][8]

// fragment scatter index: A m16n8k16 row-major bf16 fragment layout
__device__ __forceinline__ int frag_idx(int o, int j) {
    int mt = o >> 4, kt = j >> 4;
    int om = o & 15, jm = j & 15;
    int gid = om & 7, hi_m = om >> 3;
    int tig = (jm & 7) >> 1, hi_k = jm >> 3, par = jm & 1;
    int lane = gid * 4 + tig;
    return (((kt * 12 + mt) * 32 + lane) << 3) + ((hi_m + 2 * hi_k) << 1) + par;
}

// ---------------- mma helper ----------------
__device__ __forceinline__ void mma16816(float* c, const unsigned* a, const unsigned* b) {
    asm volatile(
        "mma.sync.aligned.m16n8k16.row.col.f32.bf16.bf16.f32 "
        "{%0,%1,%2,%3},{%4,%5,%6,%7},{%8,%9},{%0,%1,%2,%3};\n"
        : "+f"(c[0]), "+f"(c[1]), "+f"(c[2]), "+f"(c[3])
        : "r"(a[0]), "r"(a[1]), "r"(a[2]), "r"(a[3]), "r"(b[0]), "r"(b[1]));
}

// ---------------- LN stats + zero accumulators + proj_w fragment convert ---------
__global__ void k_stats(const float* __restrict__ x, const float* __restrict__ proj_w) {
    int i = blockIdx.x * 256 + threadIdx.x;
    if (i < CC * CC) {
        g_G[i] = 0.f;
        int o = i / CC, j = i - o * CC;
        g_Wpf[frag_idx(o, j)] = __float2bfloat16(proj_w[i]);
    }
    if (i < CC) g_s[i] = 0.f;
    int p = i;
    float s = 0.f, ss = 0.f;
#pragma unroll 8
    for (int c = 0; c < CC; c++) {
        float v = x[c * HW + p];
        s += v; ss += v * v;
    }
    float mu  = s * (1.f / CC);
    float var = ss * (1.f / CC) - mu * mu;
    g_mu[p]   = mu;
    g_rstd[p] = rsqrtf(var + 1e-5f);
}

// ---------------- fold weights ----------------
__global__ void k_fold(const float* __restrict__ qkv_w, const float* __restrict__ pre_w,
                       const float* __restrict__ ln_g, const float* __restrict__ ln_b,
                       const float* __restrict__ pre_b) {
    int o = blockIdx.x, j = threadIdx.x;
    float w2 = 0.f;
#pragma unroll 4
    for (int c = 0; c < CC; c++) w2 += qkv_w[o * CC + c] * pre_w[c * CC + j];
    float wf = w2 * ln_g[j];
    g_Wf[o * CC + j] = wf;
    if (o >= 384) g_Wvf[frag_idx(o - 384, j)] = __float2bfloat16(wf);
    __shared__ float s2[CC];
    s2[j] = w2 * ln_b[j] + qkv_w[o * CC + j] * pre_b[j];
    __syncthreads();
    if (j < 64) s2[j] += s2[j + 64] + s2[j + 128];
    __syncthreads();
    if (j < 32) {
        float b = s2[j] + s2[j + 32];
#pragma unroll
        for (int off = 16; off > 0; off >>= 1) b += __shfl_down_sync(0xffffffffu, b, off);
        if (j == 0) g_bias[o] = b;
    }
}

// ---------------- Gram of xhat: persistent, 64-pixel tiles, 384 threads ----------
#define NT64 (HW / 64)
__global__ __launch_bounds__(384) void k_gram(const float* __restrict__ x) {
    extern __shared__ __align__(16) unsigned short xs[];   // [2][CC][72]
    int tid = threadIdx.x;
    int warp = tid >> 5, lane = tid & 31, gid = lane >> 2, tig = lane & 3;
    int m0 = (warp & 3) * 48;
    int n0 = (warp >> 2) * 64;
    float acc[3][8][4];
#pragma unroll
    for (int f = 0; f < 3; f++)
#pragma unroll
        for (int g = 0; g < 8; g++)
#pragma unroll
            for (int r = 0; r < 4; r++) acc[f][g][r] = 0.f;
    float srow[8];
#pragma unroll
    for (int i = 0; i < 8; i++) srow[i] = 0.f;

    auto load_half = [&](int t, int b, int h) {
        int p0 = t * 64;
#pragma unroll
        for (int i = 0; i < 4; i++) {
            int q = tid + 384 * (h * 4 + i);
            int c = q >> 4, seg = q & 15;
            int p = p0 + seg * 4;
            float4 xv = *(const float4*)(x + c * HW + p);
            float4 m4 = *(const float4*)(g_mu + p);
            float4 r4 = *(const float4*)(g_rstd + p);
            float h0 = (xv.x - m4.x) * r4.x;
            float h1 = (xv.y - m4.y) * r4.y;
            float h2 = (xv.z - m4.z) * r4.z;
            float h3 = (xv.w - m4.w) * r4.w;
            __nv_bfloat162 lo = __floats2bfloat162_rn(h0, h1);
            __nv_bfloat162 hi = __floats2bfloat162_rn(h2, h3);
            uint2 u;
            u.x = *(unsigned*)&lo;
            u.y = *(unsigned*)&hi;
            *(uint2*)(xs + (b * CC + c) * 72 + seg * 4) = u;
            srow[h * 4 + i] += h0 + h1 + h2 + h3;
        }
    };

    int t = blockIdx.x;
    int iter = 0;
    load_half(t, 0, 0);
    load_half(t, 0, 1);
    __syncthreads();
    while (t < NT64) {
        int b = iter & 1;
        int tn = t + gridDim.x;
        if (tn < NT64) { load_half(tn, b ^ 1, 0); load_half(tn, b ^ 1, 1); }
#pragma unroll
        for (int ks = 0; ks < 4; ks++) {
            int kl = ks * 16 + 2 * tig;
            unsigned a[3][4];
#pragma unroll
            for (int f = 0; f < 3; f++) {
                int r = m0 + f * 16 + gid;
                a[f][0] = *(const unsigned*)&xs[(b * CC + r) * 72 + kl];
                a[f][1] = *(const unsigned*)&xs[(b * CC + r + 8) * 72 + kl];
                a[f][2] = *(const unsigned*)&xs[(b * CC + r) * 72 + kl + 8];
                a[f][3] = *(const unsigned*)&xs[(b * CC + r + 8) * 72 + kl + 8];
            }
#pragma unroll
            for (int g = 0; g < 8; g++) {
                int n = n0 + g * 8 + gid;
                unsigned bb[2];
                bb[0] = *(const unsigned*)&xs[(b * CC + n) * 72 + kl];
                bb[1] = *(const unsigned*)&xs[(b * CC + n) * 72 + kl + 8];
#pragma unroll
                for (int f = 0; f < 3; f++) mma16816(acc[f][g], a[f], bb);
            }
        }
        __syncthreads();
        t = tn; iter++;
    }
#pragma unroll
    for (int f = 0; f < 3; f++) {
        int m = m0 + f * 16 + gid;
#pragma unroll
        for (int g = 0; g < 8; g++) {
            int n = n0 + g * 8 + 2 * tig;
            atomicAdd(&g_G[m * CC + n],           acc[f][g][0]);
            atomicAdd(&g_G[m * CC + n + 1],       acc[f][g][1]);
            atomicAdd(&g_G[(m + 8) * CC + n],     acc[f][g][2]);
            atomicAdd(&g_G[(m + 8) * CC + n + 1], acc[f][g][3]);
        }
    }
#pragma unroll
    for (int i = 0; i < 8; i++) atomicAdd(&g_s[(tid + 384 * i) >> 4], srow[i]);
}

// ---------------- T = W_{q,k} @ G ; u = W_{q,k} @ s (parallel, 384 blocks) -------
__global__ void k_T() {
    int o = blockIdx.x, j = threadIdx.x;
    float acc = 0.f;
#pragma unroll 4
    for (int c = 0; c < CC; c++) acc += g_Wf[o * CC + c] * g_G[c * CC + j];
    g_T[o * CC + j] = acc;
    __shared__ float sh[CC];
    sh[j] = g_Wf[o * CC + j] * g_s[j];
    __syncthreads();
    if (j < 64) sh[j] += sh[j + 64] + sh[j + 128];
    __syncthreads();
    if (j < 32) {
        float a = sh[j] + sh[j + 32];
#pragma unroll
        for (int off = 16; off > 0; off >>= 1) a += __shfl_down_sync(0xffffffffu, a, off);
        if (j == 0) g_u[o] = a;
    }
}

// ---------------- attn -> mn -> gating -> gm (fragment-order bf16) ---------------
__global__ __launch_bounds__(1024) void k_gm(const float* __restrict__ mn_w,
                                             const float* __restrict__ gating) {
    int h = blockIdx.x, tid = threadIdx.x;
    int d = tid >> 5, e = tid & 31;
    __shared__ float attn[32][33];
    __shared__ float nq[32], nk[32];
    if (tid < 64) {
        int o = (tid < 32) ? (h * 32 + tid) : (CC + h * 32 + (tid - 32));
        float acc = 0.f;
        for (int c2 = 0; c2 < CC; c2++) acc += g_T[o * CC + c2] * g_Wf[o * CC + c2];
        float b = g_bias[o];
        acc += 2.f * b * g_u[o] + (float)HW * b * b;
        float nval = fmaxf(sqrtf(fmaxf(acc, 0.f)), 1e-12f);
        if (tid < 32) nq[tid] = nval; else nk[tid - 32] = nval;
    }
    __syncthreads();
    int oq = h * 32 + d, ok = CC + h * 32 + e;
    float acc = 0.f;
    for (int c2 = 0; c2 < CC; c2++) acc += g_T[oq * CC + c2] * g_Wf[ok * CC + c2];
    acc += g_bias[ok] * g_u[oq] + g_bias[oq] * g_u[ok] + (float)HW * g_bias[oq] * g_bias[ok];
    attn[d][e] = acc / (nq[d] * nk[e]);
    __syncthreads();
    float g1 = gating[h], g2 = gating[NHEAD + h];
    float acc2 = 0.f;
#pragma unroll
    for (int e2 = 0; e2 < 32; e2++)
        acc2 += attn[d][e2] * (g1 * mn_w[e * 32 + e2] + g2 * mn_w[(32 + e) * 32 + e2]);
    // scatter into fragment order: [h][ks*2+mt][lane][(hi_m+2*hi_k)*2+par]
    {
        int mt = d >> 4, ks = e >> 4;
        int om = d & 15, jm = e & 15;
        int gid2 = om & 7, hi_m = om >> 3;
        int tig2 = (jm & 7) >> 1, hi_k = jm >> 3, par = jm & 1;
        int lane2 = gid2 * 4 + tig2;
        g_gmf[h * 1024 + ((ks * 2 + mt) * 32 + lane2) * 8 + (hi_m + 2 * hi_k) * 2 + par] =
            __float2bfloat16(acc2);
    }
}

// ---------------- fused kernel: LDG.128 fragment A everywhere, LDS.32 B ----------
// smem: XH[64][200]bf16 @0, CD[64][200]bf16 @25600, TS[64][196]f32 @51200 = 101376 B
__global__ __launch_bounds__(256, 2) void k_fused(const float* __restrict__ x,
                                                  const float* __restrict__ cond,
                                                  float* __restrict__ out) {
    extern __shared__ __align__(16) char smr[];
    unsigned short* XH = (unsigned short*)(smr);
    unsigned short* CD = (unsigned short*)(smr + 25600);
    float* TS = (float*)(smr + 51200);
    int tid = threadIdx.x;
    int p0 = blockIdx.x * 64;
    int warp = tid >> 5, lane = tid & 31, gid = lane >> 2, tig = lane & 3;
    int m0 = (warp >> 1) * 48, n0 = (warp & 1) * 32;
    int mt0 = (warp >> 1) * 3;

    // ---- stage xhat (bf16) and cond (bf16), pixel-major [n][c] ----
#pragma unroll
    for (int q = tid; q < 1536; q += 256) {
        int c  = (q >> 4) * 2;
        int n4 = (q & 15) * 4;
        float4 mu4 = *(const float4*)(g_mu + p0 + n4);
        float4 rs4 = *(const float4*)(g_rstd + p0 + n4);
        float4 xa = *(const float4*)(x + c * HW + p0 + n4);
        float4 xb = *(const float4*)(x + (c + 1) * HW + p0 + n4);
        float4 ca = *(const float4*)(cond + c * HW + p0 + n4);
        float4 cb = *(const float4*)(cond + (c + 1) * HW + p0 + n4);
        float mus[4] = {mu4.x, mu4.y, mu4.z, mu4.w};
        float rss[4] = {rs4.x, rs4.y, rs4.z, rs4.w};
        float xas[4] = {xa.x, xa.y, xa.z, xa.w};
        float xbs[4] = {xb.x, xb.y, xb.z, xb.w};
        float cas[4] = {ca.x, ca.y, ca.z, ca.w};
        float cbs[4] = {cb.x, cb.y, cb.z, cb.w};
#pragma unroll
        for (int j = 0; j < 4; j++) {
            __nv_bfloat162 hx = __floats2bfloat162_rn((xas[j] - mus[j]) * rss[j],
                                                      (xbs[j] - mus[j]) * rss[j]);
            *(unsigned*)&XH[(n4 + j) * 200 + c] = *(unsigned*)&hx;
            __nv_bfloat162 hc = __floats2bfloat162_rn(cas[j], cbs[j]);
            *(unsigned*)&CD[(n4 + j) * 200 + c] = *(unsigned*)&hc;
        }
    }
    __syncthreads();

    // ---- GEMM1: v = Wv @ xhat (fragment-order LDG.128 weights) ----
    float accv[3][4][4];
#pragma unroll
    for (int f = 0; f < 3; f++)
#pragma unroll
        for (int g = 0; g < 4; g++)
#pragma unroll
            for (int r = 0; r < 4; r++) accv[f][g][r] = 0.f;
#pragma unroll
    for (int kt = 0; kt < 12; kt++) {
        uint4 a[3];
#pragma unroll
        for (int f = 0; f < 3; f++)
            a[f] = *(const uint4*)&g_Wvf[(((kt * 12) + (mt0 + f)) * 32 + lane) * 8];
        int kb = kt * 16 + 2 * tig;
#pragma unroll
        for (int g = 0; g < 4; g++) {
            int n = n0 + g * 8 + gid;
            unsigned bb[2];
            bb[0] = *(const unsigned*)&XH[n * 200 + kb];
            bb[1] = *(const unsigned*)&XH[n * 200 + kb + 8];
#pragma unroll
            for (int f = 0; f < 3; f++) mma16816(accv[f][g], (const unsigned*)&a[f], bb);
        }
    }

    // ---- GEMM2 (f-wise, block-diag gm, fragment-order A via LDG.128) ----
#pragma unroll
    for (int f = 0; f < 3; f++) {
        float accm[4][4];
#pragma unroll
        for (int g = 0; g < 4; g++)
#pragma unroll
            for (int r = 0; r < 4; r++) accm[g][r] = 0.f;
        int row16 = m0 + f * 16;
        int h = row16 >> 5;
        int mt = (row16 >> 4) & 1;
        int kkf = (row16 >> 5) << 5;
        const __nv_bfloat16* gbase = g_gmf + h * 1024;
#pragma unroll
        for (int ks = 0; ks < 2; ks++) {
            uint4 av = *(const uint4*)&gbase[((ks * 2 + mt) * 32 + lane) * 8];
            int kl = ks * 16 + 2 * tig;
#pragma unroll
            for (int g = 0; g < 4; g++) {
                int n = n0 + g * 8 + gid;
                unsigned bb[2];
                bb[0] = *(const unsigned*)&CD[n * 200 + kkf + kl];
                bb[1] = *(const unsigned*)&CD[n * 200 + kkf + kl + 8];
                mma16816(accm[g], (const unsigned*)&av, bb);
            }
        }
        float bv0 = g_bias[384 + row16 + gid];
        float bv1 = g_bias[384 + row16 + gid + 8];
#pragma unroll
        for (int g = 0; g < 4; g++) {
            accv[f][g][0] = accm[g][0] * (accv[f][g][0] + bv0);
            accv[f][g][1] = accm[g][1] * (accv[f][g][1] + bv0);
            accv[f][g][2] = accm[g][2] * (accv[f][g][2] + bv1);
            accv[f][g][3] = accm[g][3] * (accv[f][g][3] + bv1);
        }
    }

    // ---- t -> TS ----
#pragma unroll
    for (int f = 0; f < 3; f++) {
        int m = m0 + f * 16 + gid;
#pragma unroll
        for (int g = 0; g < 4; g++) {
            int n = n0 + g * 8 + 2 * tig;
            TS[n * 196 + m]           = accv[f][g][0];
            TS[(n + 1) * 196 + m]     = accv[f][g][1];
            TS[n * 196 + m + 8]       = accv[f][g][2];
            TS[(n + 1) * 196 + m + 8] = accv[f][g][3];
        }
    }
    __syncthreads();

    // ---- softmax over head-dim per pixel (vectorized LDS.128/STS.128) ----
    for (int task = tid; task < 384; task += 256) {
        int h = task >> 6, n = task & 63;
        const float* tb = TS + n * 196 + h * 32;
        float4 t4[8];
#pragma unroll
        for (int k = 0; k < 8; k++) t4[k] = *(const float4*)(tb + 4 * k);
        float mx = -1e30f;
#pragma unroll
        for (int k = 0; k < 8; k++)
            mx = fmaxf(mx, fmaxf(fmaxf(t4[k].x, t4[k].y), fmaxf(t4[k].z, t4[k].w)));
        float s = 0.f;
#pragma unroll
        for (int k = 0; k < 8; k++) {
            t4[k].x = __expf(t4[k].x - mx); t4[k].y = __expf(t4[k].y - mx);
            t4[k].z = __expf(t4[k].z - mx); t4[k].w = __expf(t4[k].w - mx);
            s += t4[k].x + t4[k].y + t4[k].z + t4[k].w;
        }
        float inv = 1.f / s;
        unsigned short* xb = XH + n * 200 + h * 32;
#pragma unroll
        for (int j = 0; j < 4; j++) {
            __nv_bfloat162 q0 = __floats2bfloat162_rn(t4[2 * j].x * inv, t4[2 * j].y * inv);
            __nv_bfloat162 q1 = __floats2bfloat162_rn(t4[2 * j].z * inv, t4[2 * j].w * inv);
            __nv_bfloat162 q2 = __floats2bfloat162_rn(t4[2 * j + 1].x * inv, t4[2 * j + 1].y * inv);
            __nv_bfloat162 q3 = __floats2bfloat162_rn(t4[2 * j + 1].z * inv, t4[2 * j + 1].w * inv);
            uint4 u;
            u.x = *(unsigned*)&q0; u.y = *(unsigned*)&q1;
            u.z = *(unsigned*)&q2; u.w = *(unsigned*)&q3;
            *(uint4*)(xb + j * 8) = u;
        }
    }
    __syncthreads();

    // ---- GEMM3: out = proj @ probs + x (fragment-order LDG.128 weights) ----
    float acc[3][4][4];
#pragma unroll
    for (int f = 0; f < 3; f++)
#pragma unroll
        for (int g = 0; g < 4; g++)
#pragma unroll
            for (int r = 0; r < 4; r++) acc[f][g][r] = 0.f;
#pragma unroll
    for (int kt = 0; kt < 12; kt++) {
        uint4 a[3];
#pragma unroll
        for (int f = 0; f < 3; f++)
            a[f] = *(const uint4*)&g_Wpf[(((kt * 12) + (mt0 + f)) * 32 + lane) * 8];
        int kb = kt * 16 + 2 * tig;
#pragma unroll
        for (int g = 0; g < 4; g++) {
            int n = n0 + g * 8 + gid;
            unsigned bb[2];
            bb[0] = *(const unsigned*)&XH[n * 200 + kb];
            bb[1] = *(const unsigned*)&XH[n * 200 + kb + 8];
#pragma unroll
            for (int f = 0; f < 3; f++) mma16816(acc[f][g], (const unsigned*)&a[f], bb);
        }
    }
#pragma unroll
    for (int f = 0; f < 3; f++) {
        int m = m0 + f * 16 + gid;
#pragma unroll
        for (int g = 0; g < 4; g++) {
            int n = n0 + g * 8 + 2 * tig;
            float2 r0 = *(const float2*)(x + m * HW + p0 + n);
            float2 r1 = *(const float2*)(x + (m + 8) * HW + p0 + n);
            float2 o0 = make_float2(acc[f][g][0] + r0.x, acc[f][g][1] + r0.y);
            float2 o1 = make_float2(acc[f][g][2] + r1.x, acc[f][g][3] + r1.y);
            *(float2*)(out + m * HW + p0 + n) = o0;
            *(float2*)(out + (m + 8) * HW + p0 + n) = o1;
        }
    }
}

// ---------------- launch ----------------
extern "C" void kernel_launch(void* const* d_in, const int* in_sizes, int n_in,
                              void* d_out, int out_size) {
    const float* x      = (const float*)d_in[0];
    const float* cond   = (const float*)d_in[1];
    const float* ln_g   = (const float*)d_in[2];
    const float* ln_b   = (const float*)d_in[3];
    const float* pre_w  = (const float*)d_in[4];
    const float* pre_b  = (const float*)d_in[5];
    const float* qkv_w  = (const float*)d_in[6];
    const float* mn_w   = (const float*)d_in[7];
    const float* gating = (const float*)d_in[8];
    const float* proj_w = (const float*)d_in[9];
    float* out = (float*)d_out;

    cudaFuncSetAttribute(k_fused, cudaFuncAttributeMaxDynamicSharedMemorySize, 101376);
    cudaFuncSetAttribute(k_gram, cudaFuncAttributeMaxDynamicSharedMemorySize, 55296);

    k_stats<<<HW / 256, 256>>>(x, proj_w);                  // 1 (+zero +cvt)
    k_fold<<<576, CC>>>(qkv_w, pre_w, ln_g, ln_b, pre_b);   // 2
    k_gram<<<148, 384, 55296>>>(x);                         // 3
    k_T<<<384, CC>>>();                                     // 4
    k_gm<<<NHEAD, 1024>>>(mn_w, gating);                    // 5
    k_fused<<<HW / 64, 256, 101376>>>(x, cond, out);        // 6
}

// round 17
// speedup vs baseline: 1.3933x; 1.0001x over previous
#include <cuda_runtime.h>
#include <cuda_bf16.h>
#include <math.h>

#define HW 200704
#define CC 192
#define NHEAD 6

// ---------------- scratch ----------------
__device__ float g_mu[HW];
__device__ float g_rstd[HW];
__device__ float g_Wf[576 * CC];
__device__ float g_bias[576];
__device__ float g_G[CC * CC];
__device__ float g_s[CC];
__device__ __align__(16) __nv_bfloat16 g_Wvf[CC * CC];   // v weight, mma-fragment order
__device__ __align__(16) __nv_bfloat16 g_Wpf[CC * CC];   // proj weight, mma-fragment order
__device__ __align__(16) __nv_bfloat16 g_gmf[CC * 32];   // gm blocks, fragment order [h][ks*2+mt][lane][8]

// fragment scatter index: A m16n8k16 row-major bf16 fragment layout
__device__ __forceinline__ int frag_idx(int o, int j) {
    int mt = o >> 4, kt = j >> 4;
    int om = o & 15, jm = j & 15;
    int gid = om & 7, hi_m = om >> 3;
    int tig = (jm & 7) >> 1, hi_k = jm >> 3, par = jm & 1;
    int lane = gid * 4 + tig;
    return (((kt * 12 + mt) * 32 + lane) << 3) + ((hi_m + 2 * hi_k) << 1) + par;
}

// ---------------- mma helper ----------------
__device__ __forceinline__ void mma16816(float* c, const unsigned* a, const unsigned* b) {
    asm volatile(
        "mma.sync.aligned.m16n8k16.row.col.f32.bf16.bf16.f32 "
        "{%0,%1,%2,%3},{%4,%5,%6,%7},{%8,%9},{%0,%1,%2,%3};\n"
        : "+f"(c[0]), "+f"(c[1]), "+f"(c[2]), "+f"(c[3])
        : "r"(a[0]), "r"(a[1]), "r"(a[2]), "r"(a[3]), "r"(b[0]), "r"(b[1]));
}

// ---------------- k_pre: LN stats + zero + Wpf cvt (blocks 0-783) | fold (784-1359)
__global__ __launch_bounds__(256) void k_pre(const float* __restrict__ x,
                                             const float* __restrict__ proj_w,
                                             const float* __restrict__ qkv_w,
                                             const float* __restrict__ pre_w,
                                             const float* __restrict__ ln_g,
                                             const float* __restrict__ ln_b,
                                             const float* __restrict__ pre_b) {
    if (blockIdx.x < 784) {
        int i = blockIdx.x * 256 + threadIdx.x;
        if (i < CC * CC) {
            g_G[i] = 0.f;
            int o = i / CC, j = i - o * CC;
            g_Wpf[frag_idx(o, j)] = __float2bfloat16(proj_w[i]);
        }
        if (i < CC) g_s[i] = 0.f;
        int p = i;
        float s = 0.f, ss = 0.f;
#pragma unroll 8
        for (int c = 0; c < CC; c++) {
            float v = x[c * HW + p];
            s += v; ss += v * v;
        }
        float mu  = s * (1.f / CC);
        float var = ss * (1.f / CC) - mu * mu;
        g_mu[p]   = mu;
        g_rstd[p] = rsqrtf(var + 1e-5f);
    } else {
        int o = blockIdx.x - 784;
        int j = threadIdx.x;
        __shared__ float s2[CC];
        float wf = 0.f;
        if (j < CC) {
            float w2 = 0.f;
#pragma unroll 4
            for (int c = 0; c < CC; c++) w2 += qkv_w[o * CC + c] * pre_w[c * CC + j];
            wf = w2 * ln_g[j];
            g_Wf[o * CC + j] = wf;
            if (o >= 384) g_Wvf[frag_idx(o - 384, j)] = __float2bfloat16(wf);
            s2[j] = w2 * ln_b[j] + qkv_w[o * CC + j] * pre_b[j];
        }
        __syncthreads();
        if (j < 64) s2[j] += s2[j + 64] + s2[j + 128];
        __syncthreads();
        if (j < 32) {
            float b = s2[j] + s2[j + 32];
#pragma unroll
            for (int off = 16; off > 0; off >>= 1) b += __shfl_down_sync(0xffffffffu, b, off);
            if (j == 0) g_bias[o] = b;
        }
    }
}

// ---------------- Gram of xhat: persistent, 64-pixel tiles, 384 threads ----------
#define NT64 (HW / 64)
__global__ __launch_bounds__(384) void k_gram(const float* __restrict__ x) {
    extern __shared__ __align__(16) unsigned short xs[];   // [2][CC][72]
    int tid = threadIdx.x;
    int warp = tid >> 5, lane = tid & 31, gid = lane >> 2, tig = lane & 3;
    int m0 = (warp & 3) * 48;
    int n0 = (warp >> 2) * 64;
    float acc[3][8][4];
#pragma unroll
    for (int f = 0; f < 3; f++)
#pragma unroll
        for (int g = 0; g < 8; g++)
#pragma unroll
            for (int r = 0; r < 4; r++) acc[f][g][r] = 0.f;
    float srow[8];
#pragma unroll
    for (int i = 0; i < 8; i++) srow[i] = 0.f;

    auto load_half = [&](int t, int b, int h) {
        int p0 = t * 64;
#pragma unroll
        for (int i = 0; i < 4; i++) {
            int q = tid + 384 * (h * 4 + i);
            int c = q >> 4, seg = q & 15;
            int p = p0 + seg * 4;
            float4 xv = *(const float4*)(x + c * HW + p);
            float4 m4 = *(const float4*)(g_mu + p);
            float4 r4 = *(const float4*)(g_rstd + p);
            float h0 = (xv.x - m4.x) * r4.x;
            float h1 = (xv.y - m4.y) * r4.y;
            float h2 = (xv.z - m4.z) * r4.z;
            float h3 = (xv.w - m4.w) * r4.w;
            __nv_bfloat162 lo = __floats2bfloat162_rn(h0, h1);
            __nv_bfloat162 hi = __floats2bfloat162_rn(h2, h3);
            uint2 u;
            u.x = *(unsigned*)&lo;
            u.y = *(unsigned*)&hi;
            *(uint2*)(xs + (b * CC + c) * 72 + seg * 4) = u;
            srow[h * 4 + i] += h0 + h1 + h2 + h3;
        }
    };

    int t = blockIdx.x;
    int iter = 0;
    load_half(t, 0, 0);
    load_half(t, 0, 1);
    __syncthreads();
    while (t < NT64) {
        int b = iter & 1;
        int tn = t + gridDim.x;
        if (tn < NT64) { load_half(tn, b ^ 1, 0); load_half(tn, b ^ 1, 1); }
#pragma unroll
        for (int ks = 0; ks < 4; ks++) {
            int kl = ks * 16 + 2 * tig;
            unsigned a[3][4];
#pragma unroll
            for (int f = 0; f < 3; f++) {
                int r = m0 + f * 16 + gid;
                a[f][0] = *(const unsigned*)&xs[(b * CC + r) * 72 + kl];
                a[f][1] = *(const unsigned*)&xs[(b * CC + r + 8) * 72 + kl];
                a[f][2] = *(const unsigned*)&xs[(b * CC + r) * 72 + kl + 8];
                a[f][3] = *(const unsigned*)&xs[(b * CC + r + 8) * 72 + kl + 8];
            }
#pragma unroll
            for (int g = 0; g < 8; g++) {
                int n = n0 + g * 8 + gid;
                unsigned bb[2];
                bb[0] = *(const unsigned*)&xs[(b * CC + n) * 72 + kl];
                bb[1] = *(const unsigned*)&xs[(b * CC + n) * 72 + kl + 8];
#pragma unroll
                for (int f = 0; f < 3; f++) mma16816(acc[f][g], a[f], bb);
            }
        }
        __syncthreads();
        t = tn; iter++;
    }
#pragma unroll
    for (int f = 0; f < 3; f++) {
        int m = m0 + f * 16 + gid;
#pragma unroll
        for (int g = 0; g < 8; g++) {
            int n = n0 + g * 8 + 2 * tig;
            atomicAdd(&g_G[m * CC + n],           acc[f][g][0]);
            atomicAdd(&g_G[m * CC + n + 1],       acc[f][g][1]);
            atomicAdd(&g_G[(m + 8) * CC + n],     acc[f][g][2]);
            atomicAdd(&g_G[(m + 8) * CC + n + 1], acc[f][g][3]);
        }
    }
#pragma unroll
    for (int i = 0; i < 8; i++) atomicAdd(&g_s[(tid + 384 * i) >> 4], srow[i]);
}

// ---------------- k_attn: per-head G->P (smem) -> norms -> attn -> mn -> gm ------
// smem floats: Gs[192*192]@0, Ps[64*192]@36864, ss[192]@49152, uu[64]@49344,
//              nq[32]@49408, nk[32]@49440, attn[32*33]@49472 ; 50528 f = 202112 B
__global__ __launch_bounds__(1024) void k_attn(const float* __restrict__ mn_w,
                                               const float* __restrict__ gating) {
    extern __shared__ float sm[];
    float* Gs   = sm;
    float* Ps   = sm + 36864;
    float* ss   = sm + 49152;
    float* uu   = sm + 49344;
    float* nq   = sm + 49408;
    float* nk   = sm + 49440;
    float* attn = sm + 49472;
    int h = blockIdx.x, tid = threadIdx.x;

    // stage G (f32) and s
#pragma unroll
    for (int i = 0; i < 9; i++)
        ((float4*)Gs)[tid + 1024 * i] = ((const float4*)g_G)[tid + 1024 * i];
    if (tid < 48) ((float4*)ss)[tid] = ((const float4*)g_s)[tid];
    __syncthreads();

    // P[lr][j] = sum_c Wf[o][c] * G[c][j], lr 0..31 = q rows, 32..63 = k rows
    int lr = tid >> 4, jt = tid & 15;
    int o = (lr < 32) ? (h * 32 + lr) : (CC + h * 32 + (lr - 32));
    const float* wrow = g_Wf + o * CC;
    {
        float acc[12];
#pragma unroll
        for (int r = 0; r < 12; r++) acc[r] = 0.f;
#pragma unroll 4
        for (int c = 0; c < CC; c++) {
            float wv = wrow[c];
            const float* gr = Gs + c * CC + jt * 12;
            float4 g0 = *(const float4*)(gr);
            float4 g1 = *(const float4*)(gr + 4);
            float4 g2 = *(const float4*)(gr + 8);
            acc[0] += wv * g0.x; acc[1] += wv * g0.y; acc[2] += wv * g0.z; acc[3] += wv * g0.w;
            acc[4] += wv * g1.x; acc[5] += wv * g1.y; acc[6] += wv * g1.z; acc[7] += wv * g1.w;
            acc[8] += wv * g2.x; acc[9] += wv * g2.y; acc[10] += wv * g2.z; acc[11] += wv * g2.w;
        }
        float* pr = Ps + lr * CC + jt * 12;
#pragma unroll
        for (int r = 0; r < 12; r++) pr[r] = acc[r];
    }
    __syncthreads();

    // u and norms (tid < 64)
    if (tid < 64) {
        int l2 = tid;
        int o2 = (l2 < 32) ? (h * 32 + l2) : (CC + h * 32 + (l2 - 32));
        const float* w2 = g_Wf + o2 * CC;
        float au = 0.f, acc = 0.f;
        for (int c = 0; c < CC; c++) {
            au  += w2[c] * ss[c];
            acc += Ps[l2 * CC + c] * w2[c];
        }
        uu[l2] = au;
        float b = g_bias[o2];
        acc += 2.f * b * au + (float)HW * b * b;
        float nval = fmaxf(sqrtf(fmaxf(acc, 0.f)), 1e-12f);
        if (l2 < 32) nq[l2] = nval; else nk[l2 - 32] = nval;
    }
    __syncthreads();

    // attn[d][e]
    int d = tid >> 5, e = tid & 31;
    int oq = h * 32 + d, ok = CC + h * 32 + e;
    const float* wk = g_Wf + ok * CC;
    float acc = 0.f;
    for (int c = 0; c < CC; c++) acc += Ps[d * CC + c] * wk[c];
    acc += g_bias[ok] * uu[d] + g_bias[oq] * uu[32 + e] + (float)HW * g_bias[oq] * g_bias[ok];
    attn[d * 33 + e] = acc / (nq[d] * nk[e]);
    __syncthreads();

    // mn + gating -> gm, scatter to fragment order
    float g1 = gating[h], g2 = gating[NHEAD + h];
    float acc2 = 0.f;
#pragma unroll
    for (int e2 = 0; e2 < 32; e2++)
        acc2 += attn[d * 33 + e2] * (g1 * mn_w[e * 32 + e2] + g2 * mn_w[(32 + e) * 32 + e2]);
    {
        int mt = d >> 4, ks = e >> 4;
        int om = d & 15, jm = e & 15;
        int gid2 = om & 7, hi_m = om >> 3;
        int tig2 = (jm & 7) >> 1, hi_k = jm >> 3, par = jm & 1;
        int lane2 = gid2 * 4 + tig2;
        g_gmf[h * 1024 + ((ks * 2 + mt) * 32 + lane2) * 8 + (hi_m + 2 * hi_k) * 2 + par] =
            __float2bfloat16(acc2);
    }
}

// ---------------- fused kernel: LDG.128 fragment A everywhere, LDS.32 B ----------
// smem: XH[64][200]bf16 @0, CD[64][200]bf16 @25600, TS[64][196]f32 @51200 = 101376 B
__global__ __launch_bounds__(256, 2) void k_fused(const float* __restrict__ x,
                                                  const float* __restrict__ cond,
                                                  float* __restrict__ out) {
    extern __shared__ __align__(16) char smr[];
    unsigned short* XH = (unsigned short*)(smr);
    unsigned short* CD = (unsigned short*)(smr + 25600);
    float* TS = (float*)(smr + 51200);
    int tid = threadIdx.x;
    int p0 = blockIdx.x * 64;
    int warp = tid >> 5, lane = tid & 31, gid = lane >> 2, tig = lane & 3;
    int m0 = (warp >> 1) * 48, n0 = (warp & 1) * 32;
    int mt0 = (warp >> 1) * 3;

    // ---- stage xhat (bf16) and cond (bf16), pixel-major [n][c] ----
#pragma unroll
    for (int q = tid; q < 1536; q += 256) {
        int c  = (q >> 4) * 2;
        int n4 = (q & 15) * 4;
        float4 mu4 = *(const float4*)(g_mu + p0 + n4);
        float4 rs4 = *(const float4*)(g_rstd + p0 + n4);
        float4 xa = *(const float4*)(x + c * HW + p0 + n4);
        float4 xb = *(const float4*)(x + (c + 1) * HW + p0 + n4);
        float4 ca = *(const float4*)(cond + c * HW + p0 + n4);
        float4 cb = *(const float4*)(cond + (c + 1) * HW + p0 + n4);
        float mus[4] = {mu4.x, mu4.y, mu4.z, mu4.w};
        float rss[4] = {rs4.x, rs4.y, rs4.z, rs4.w};
        float xas[4] = {xa.x, xa.y, xa.z, xa.w};
        float xbs[4] = {xb.x, xb.y, xb.z, xb.w};
        float cas[4] = {ca.x, ca.y, ca.z, ca.w};
        float cbs[4] = {cb.x, cb.y, cb.z, cb.w};
#pragma unroll
        for (int j = 0; j < 4; j++) {
            __nv_bfloat162 hx = __floats2bfloat162_rn((xas[j] - mus[j]) * rss[j],
                                                      (xbs[j] - mus[j]) * rss[j]);
            *(unsigned*)&XH[(n4 + j) * 200 + c] = *(unsigned*)&hx;
            __nv_bfloat162 hc = __floats2bfloat162_rn(cas[j], cbs[j]);
            *(unsigned*)&CD[(n4 + j) * 200 + c] = *(unsigned*)&hc;
        }
    }
    __syncthreads();

    // ---- GEMM1: v = Wv @ xhat (fragment-order LDG.128 weights) ----
    float accv[3][4][4];
#pragma unroll
    for (int f = 0; f < 3; f++)
#pragma unroll
        for (int g = 0; g < 4; g++)
#pragma unroll
            for (int r = 0; r < 4; r++) accv[f][g][r] = 0.f;
#pragma unroll
    for (int kt = 0; kt < 12; kt++) {
        uint4 a[3];
#pragma unroll
        for (int f = 0; f < 3; f++)
            a[f] = *(const uint4*)&g_Wvf[(((kt * 12) + (mt0 + f)) * 32 + lane) * 8];
        int kb = kt * 16 + 2 * tig;
#pragma unroll
        for (int g = 0; g < 4; g++) {
            int n = n0 + g * 8 + gid;
            unsigned bb[2];
            bb[0] = *(const unsigned*)&XH[n * 200 + kb];
            bb[1] = *(const unsigned*)&XH[n * 200 + kb + 8];
#pragma unroll
            for (int f = 0; f < 3; f++) mma16816(accv[f][g], (const unsigned*)&a[f], bb);
        }
    }

    // ---- GEMM2 (f-wise, block-diag gm, fragment-order A via LDG.128) ----
#pragma unroll
    for (int f = 0; f < 3; f++) {
        float accm[4][4];
#pragma unroll
        for (int g = 0; g < 4; g++)
#pragma unroll
            for (int r = 0; r < 4; r++) accm[g][r] = 0.f;
        int row16 = m0 + f * 16;
        int h = row16 >> 5;
        int mt = (row16 >> 4) & 1;
        int kkf = (row16 >> 5) << 5;
        const __nv_bfloat16* gbase = g_gmf + h * 1024;
#pragma unroll
        for (int ks = 0; ks < 2; ks++) {
            uint4 av = *(const uint4*)&gbase[((ks * 2 + mt) * 32 + lane) * 8];
            int kl = ks * 16 + 2 * tig;
#pragma unroll
            for (int g = 0; g < 4; g++) {
                int n = n0 + g * 8 + gid;
                unsigned bb[2];
                bb[0] = *(const unsigned*)&CD[n * 200 + kkf + kl];
                bb[1] = *(const unsigned*)&CD[n * 200 + kkf + kl + 8];
                mma16816(accm[g], (const unsigned*)&av, bb);
            }
        }
        float bv0 = g_bias[384 + row16 + gid];
        float bv1 = g_bias[384 + row16 + gid + 8];
#pragma unroll
        for (int g = 0; g < 4; g++) {
            accv[f][g][0] = accm[g][0] * (accv[f][g][0] + bv0);
            accv[f][g][1] = accm[g][1] * (accv[f][g][1] + bv0);
            accv[f][g][2] = accm[g][2] * (accv[f][g][2] + bv1);
            accv[f][g][3] = accm[g][3] * (accv[f][g][3] + bv1);
        }
    }

    // ---- t -> TS ----
#pragma unroll
    for (int f = 0; f < 3; f++) {
        int m = m0 + f * 16 + gid;
#pragma unroll
        for (int g = 0; g < 4; g++) {
            int n = n0 + g * 8 + 2 * tig;
            TS[n * 196 + m]           = accv[f][g][0];
            TS[(n + 1) * 196 + m]     = accv[f][g][1];
            TS[n * 196 + m + 8]       = accv[f][g][2];
            TS[(n + 1) * 196 + m + 8] = accv[f][g][3];
        }
    }
    __syncthreads();

    // ---- softmax over head-dim per pixel (vectorized LDS.128/STS.128) ----
    for (int task = tid; task < 384; task += 256) {
        int h = task >> 6, n = task & 63;
        const float* tb = TS + n * 196 + h * 32;
        float4 t4[8];
#pragma unroll
        for (int k = 0; k < 8; k++) t4[k] = *(const float4*)(tb + 4 * k);
        float mx = -1e30f;
#pragma unroll
        for (int k = 0; k < 8; k++)
            mx = fmaxf(mx, fmaxf(fmaxf(t4[k].x, t4[k].y), fmaxf(t4[k].z, t4[k].w)));
        float s = 0.f;
#pragma unroll
        for (int k = 0; k < 8; k++) {
            t4[k].x = __expf(t4[k].x - mx); t4[k].y = __expf(t4[k].y - mx);
            t4[k].z = __expf(t4[k].z - mx); t4[k].w = __expf(t4[k].w - mx);
            s += t4[k].x + t4[k].y + t4[k].z + t4[k].w;
        }
        float inv = 1.f / s;
        unsigned short* xb = XH + n * 200 + h * 32;
#pragma unroll
        for (int j = 0; j < 4; j++) {
            __nv_bfloat162 q0 = __floats2bfloat162_rn(t4[2 * j].x * inv, t4[2 * j].y * inv);
            __nv_bfloat162 q1 = __floats2bfloat162_rn(t4[2 * j].z * inv, t4[2 * j].w * inv);
            __nv_bfloat162 q2 = __floats2bfloat162_rn(t4[2 * j + 1].x * inv, t4[2 * j + 1].y * inv);
            __nv_bfloat162 q3 = __floats2bfloat162_rn(t4[2 * j + 1].z * inv, t4[2 * j + 1].w * inv);
            uint4 u;
            u.x = *(unsigned*)&q0; u.y = *(unsigned*)&q1;
            u.z = *(unsigned*)&q2; u.w = *(unsigned*)&q3;
            *(uint4*)(xb + j * 8) = u;
        }
    }
    __syncthreads();

    // ---- GEMM3: out = proj @ probs + x (fragment-order LDG.128 weights) ----
    float acc[3][4][4];
#pragma unroll
    for (int f = 0; f < 3; f++)
#pragma unroll
        for (int g = 0; g < 4; g++)
#pragma unroll
            for (int r = 0; r < 4; r++) acc[f][g][r] = 0.f;
#pragma unroll
    for (int kt = 0; kt < 12; kt++) {
        uint4 a[3];
#pragma unroll
        for (int f = 0; f < 3; f++)
            a[f] = *(const uint4*)&g_Wpf[(((kt * 12) + (mt0 + f)) * 32 + lane) * 8];
        int kb = kt * 16 + 2 * tig;
#pragma unroll
        for (int g = 0; g < 4; g++) {
            int n = n0 + g * 8 + gid;
            unsigned bb[2];
            bb[0] = *(const unsigned*)&XH[n * 200 + kb];
            bb[1] = *(const unsigned*)&XH[n * 200 + kb + 8];
#pragma unroll
            for (int f = 0; f < 3; f++) mma16816(acc[f][g], (const unsigned*)&a[f], bb);
        }
    }
#pragma unroll
    for (int f = 0; f < 3; f++) {
        int m = m0 + f * 16 + gid;
#pragma unroll
        for (int g = 0; g < 4; g++) {
            int n = n0 + g * 8 + 2 * tig;
            float2 r0 = *(const float2*)(x + m * HW + p0 + n);
            float2 r1 = *(const float2*)(x + (m + 8) * HW + p0 + n);
            float2 o0 = make_float2(acc[f][g][0] + r0.x, acc[f][g][1] + r0.y);
            float2 o1 = make_float2(acc[f][g][2] + r1.x, acc[f][g][3] + r1.y);
            *(float2*)(out + m * HW + p0 + n) = o0;
            *(float2*)(out + (m + 8) * HW + p0 + n) = o1;
        }
    }
}

// ---------------- launch ----------------
extern "C" void kernel_launch(void* const* d_in, const int* in_sizes, int n_in,
                              void* d_out, int out_size) {
    const float* x      = (const float*)d_in[0];
    const float* cond   = (const float*)d_in[1];
    const float* ln_g   = (const float*)d_in[2];
    const float* ln_b   = (const float*)d_in[3];
    const float* pre_w  = (const float*)d_in[4];
    const float* pre_b  = (const float*)d_in[5];
    const float* qkv_w  = (const float*)d_in[6];
    const float* mn_w   = (const float*)d_in[7];
    const float* gating = (const float*)d_in[8];
    const float* proj_w = (const float*)d_in[9];
    float* out = (float*)d_out;

    cudaFuncSetAttribute(k_fused, cudaFuncAttributeMaxDynamicSharedMemorySize, 101376);
    cudaFuncSetAttribute(k_gram, cudaFuncAttributeMaxDynamicSharedMemorySize, 55296);
    cudaFuncSetAttribute(k_attn, cudaFuncAttributeMaxDynamicSharedMemorySize, 202112);

    k_pre<<<1360, 256>>>(x, proj_w, qkv_w, pre_w, ln_g, ln_b, pre_b);  // 1
    k_gram<<<148, 384, 55296>>>(x);                                    // 2
    k_attn<<<NHEAD, 1024, 202112>>>(mn_w, gating);                     // 3
    k_fused<<<HW / 64, 256, 101376>>>(x, cond, out);                   // 4  (profiled)
}